// round 6
// baseline (speedup 1.0000x reference)
#include <cuda_runtime.h>

#define NT 192
#define XS   36    // X/H row stride (floats) — 144B rotates banks
#define PJS  68    // Pj row stride
#define HIDS 68    // emb hidden row stride
#define ATTS 52

// shared layout (float offsets)
#define OFF_X    0        // 51*36 = 1836
#define OFF_H    1840     // 51*36 = 1836
#define OFF_PI   3680     // emb hidden 50*68+64=3464 / Pi 51*64=3264 / mlp scratch
#define OFF_PJ   7216     // 51*68 = 3468
#define OFF_ATT  10688    // 51*52 = 2652
#define OFF_W    13344    // 4288 weight staging
#define OFF_ST   17632    // 750 state row
#define OFF_O    18384    // 64
#define SMEM_FLOATS 18448
#define ROBOT_HID 3468    // robot hidden inside PI region

__device__ __forceinline__ void fma4(float4& acc, float s, const float4 w) {
    acc.x = fmaf(s, w.x, acc.x);
    acc.y = fmaf(s, w.y, acc.y);
    acc.z = fmaf(s, w.z, acc.z);
    acc.w = fmaf(s, w.w, acc.w);
}
__device__ __forceinline__ float comp(const float4 v, int s) {
    return s == 0 ? v.x : s == 1 ? v.y : s == 2 ? v.z : v.w;
}
__device__ __forceinline__ void relu4(float4& a) {
    a.x = fmaxf(a.x, 0.f); a.y = fmaxf(a.y, 0.f);
    a.z = fmaxf(a.z, 0.f); a.w = fmaxf(a.w, 0.f);
}

__device__ __forceinline__ void softmax_row(
    float accA, float accB, float b1v, int i, int lane, int jb, bool vb,
    float* __restrict__ sAtt)
{
    float Aa = accA + b1v;
    float Ab = accB + b1v;
    float ea = Aa > 0.f ? Aa : 0.04f * Aa;   // leaky relu
    float eb = Ab > 0.f ? Ab : 0.04f * Ab;
    bool va = (i == 0) || (lane != 0);       // adj: rows >=1 exclude j==0
    float m = fmaxf(va ? ea : -3.0e38f, vb ? eb : -3.0e38f);
    #pragma unroll
    for (int off = 16; off > 0; off >>= 1)
        m = fmaxf(m, __shfl_xor_sync(0xffffffffu, m, off));
    float pa = va ? __expf(ea - m) : 0.f;
    float pb = vb ? __expf(eb - m) : 0.f;
    float s = pa + pb;
    #pragma unroll
    for (int off = 16; off > 0; off >>= 1)
        s += __shfl_xor_sync(0xffffffffu, s, off);
    float inv = 1.0f / s;
    sAtt[i * ATTS + lane] = pa * inv;
    if (vb) sAtt[i * ATTS + jb] = pb * inv;
}

template<bool FULL>
__device__ __forceinline__ void gat_layer(
    float* sm, const float* __restrict__ Xin, float* __restrict__ Hout,
    const float* __restrict__ gw0, const float* __restrict__ gb0,
    const float* __restrict__ gw1, const float* __restrict__ gb1,
    int tid, int wid, int lane)
{
    float* sPi  = sm + OFF_PI;
    float* sPj  = sm + OFF_PJ;
    float* sAtt = sm + OFF_ATT;
    float* sW   = sm + OFF_W;

    // ---- stage weights: gw0 (64x64) -> sW[0..4095], b0 -> 4096, w1 -> 4160, b1 -> 4224
    {
        float4* dst = (float4*)sW;
        const float4* src = (const float4*)gw0;
        for (int i = tid; i < 1024; i += NT) dst[i] = src[i];
        if (tid < 64)            sW[4096 + tid]        = gb0[tid];
        else if (tid < 128)      sW[4160 + (tid - 64)] = gw1[tid - 64];
        else if (tid == 128)     sW[4224]              = gb1[0];
    }
    __syncthreads();

    // ---- P phase: 4 nodes x 4 cols outer-product tile per 16-thread group
    {
        int tq = tid & 15;
        for (int nq = tid >> 4; nq < 13; nq += NT / 16) {
            int n0 = nq * 4;
            const float4* x0 = (const float4*)(Xin + (n0 + 0) * XS);
            const float4* x1 = (const float4*)(Xin + (n0 + 1) * XS);
            const float4* x2 = (const float4*)(Xin + (n0 + 2) * XS);
            const float4* x3 = (const float4*)(Xin + (n0 + 3) * XS);
            float4 z = make_float4(0.f, 0.f, 0.f, 0.f);
            float4 aJ0 = z, aJ1 = z, aJ2 = z, aJ3 = z;
            float4 bI = ((const float4*)(sW + 4096))[tq];
            float4 aI0 = bI, aI1 = bI, aI2 = bI, aI3 = bI;
            #pragma unroll 4
            for (int f4 = 0; f4 < 8; f4++) {
                float4 xv0 = x0[f4], xv1 = x1[f4], xv2 = x2[f4], xv3 = x3[f4];
                #pragma unroll
                for (int s = 0; s < 4; s++) {
                    int f = f4 * 4 + s;
                    float4 wJ = ((const float4*)(sW + (f + 32) * 64))[tq];
                    float e0 = comp(xv0, s), e1 = comp(xv1, s);
                    float e2 = comp(xv2, s), e3 = comp(xv3, s);
                    if (FULL) {
                        float4 wI = ((const float4*)(sW + f * 64))[tq];
                        fma4(aI0, e0, wI); fma4(aI1, e1, wI);
                        fma4(aI2, e2, wI); fma4(aI3, e3, wI);
                    }
                    fma4(aJ0, e0, wJ); fma4(aJ1, e1, wJ);
                    fma4(aJ2, e2, wJ); fma4(aJ3, e3, wJ);
                }
            }
            if (FULL) {
                ((float4*)(sPi + (n0 + 0) * 64))[tq] = aI0;
                ((float4*)(sPi + (n0 + 1) * 64))[tq] = aI1;
                ((float4*)(sPi + (n0 + 2) * 64))[tq] = aI2;
                if (n0 + 3 < 51) ((float4*)(sPi + (n0 + 3) * 64))[tq] = aI3;
            }
            ((float4*)(sPj + (n0 + 0) * PJS))[tq] = aJ0;
            ((float4*)(sPj + (n0 + 1) * PJS))[tq] = aJ1;
            ((float4*)(sPj + (n0 + 2) * PJS))[tq] = aJ2;
            if (n0 + 3 < 51) ((float4*)(sPj + (n0 + 3) * PJS))[tq] = aJ3;
        }
        if (!FULL && tid < 16) {    // Pi only for row 0
            int q = tid;
            const float4* x4p = (const float4*)Xin;
            float4 aI = ((const float4*)(sW + 4096))[q];
            #pragma unroll
            for (int f4 = 0; f4 < 8; f4++) {
                float4 xv = x4p[f4];
                #pragma unroll
                for (int s = 0; s < 4; s++) {
                    float4 wI = ((const float4*)(sW + (f4 * 4 + s) * 64))[q];
                    fma4(aI, comp(xv, s), wI);
                }
            }
            ((float4*)sPi)[q] = aI;
        }
    }
    __syncthreads();

    const int NR = FULL ? 51 : 1;
    const int NW = NT / 32;           // 6 warps

    // ---- pair phase, 2 rows per iteration (pa/pb/w1 reused across both rows)
    for (int i0 = wid; i0 < NR; i0 += 2 * NW) {
        int i1 = i0 + NW;
        bool has1 = i1 < NR;
        int i1c = has1 ? i1 : i0;
        int jb  = lane + 32;
        int jbc = jb < 51 ? jb : 50;       // clamp keeps LDS conflict-free
        const float4* p0v = (const float4*)(sPi + i0 * 64);
        const float4* p1v = (const float4*)(sPi + i1c * 64);
        const float4* w1v = (const float4*)(sW + 4160);
        const float4* pav = (const float4*)(sPj + lane * PJS);
        const float4* pbv = (const float4*)(sPj + jbc * PJS);
        float aA0 = 0.f, aB0 = 0.f, aA1 = 0.f, aB1 = 0.f;
        #pragma unroll 8
        for (int c4 = 0; c4 < 16; c4++) {
            float4 pa = pav[c4];
            float4 pb = pbv[c4];
            float4 w1 = w1v[c4];
            float4 p0 = p0v[c4];
            float4 p1 = p1v[c4];
            aA0 = fmaf(fmaxf(p0.x + pa.x, 0.f), w1.x, aA0);
            aA0 = fmaf(fmaxf(p0.y + pa.y, 0.f), w1.y, aA0);
            aA0 = fmaf(fmaxf(p0.z + pa.z, 0.f), w1.z, aA0);
            aA0 = fmaf(fmaxf(p0.w + pa.w, 0.f), w1.w, aA0);
            aB0 = fmaf(fmaxf(p0.x + pb.x, 0.f), w1.x, aB0);
            aB0 = fmaf(fmaxf(p0.y + pb.y, 0.f), w1.y, aB0);
            aB0 = fmaf(fmaxf(p0.z + pb.z, 0.f), w1.z, aB0);
            aB0 = fmaf(fmaxf(p0.w + pb.w, 0.f), w1.w, aB0);
            aA1 = fmaf(fmaxf(p1.x + pa.x, 0.f), w1.x, aA1);
            aA1 = fmaf(fmaxf(p1.y + pa.y, 0.f), w1.y, aA1);
            aA1 = fmaf(fmaxf(p1.z + pa.z, 0.f), w1.z, aA1);
            aA1 = fmaf(fmaxf(p1.w + pa.w, 0.f), w1.w, aA1);
            aB1 = fmaf(fmaxf(p1.x + pb.x, 0.f), w1.x, aB1);
            aB1 = fmaf(fmaxf(p1.y + pb.y, 0.f), w1.y, aB1);
            aB1 = fmaf(fmaxf(p1.z + pb.z, 0.f), w1.z, aB1);
            aB1 = fmaf(fmaxf(p1.w + pb.w, 0.f), w1.w, aB1);
        }
        float b1v = sW[4224];
        bool vb = jb < 51;
        softmax_row(aA0, aB0, b1v, i0, lane, jb, vb, sAtt);
        if (has1) softmax_row(aA1, aB1, b1v, i1, lane, jb, vb, sAtt);
    }
    __syncthreads();

    // ---- H = att @ Xin, 2 rows per iteration (X loads shared)
    for (int i0 = wid; i0 < NR; i0 += 2 * NW) {
        int i1 = i0 + NW;
        bool has1 = i1 < NR;
        int i1c = has1 ? i1 : i0;
        const float* a0 = sAtt + i0 * ATTS;
        const float* a1 = sAtt + i1c * ATTS;
        const float4* a04 = (const float4*)a0;
        const float4* a14 = (const float4*)a1;
        float acc0 = 0.f, acc1 = 0.f;
        #pragma unroll
        for (int j4 = 0; j4 < 12; j4++) {
            float4 v0 = a04[j4];
            float4 v1 = a14[j4];
            float xa = Xin[(j4 * 4 + 0) * XS + lane];
            float xb = Xin[(j4 * 4 + 1) * XS + lane];
            float xc = Xin[(j4 * 4 + 2) * XS + lane];
            float xd = Xin[(j4 * 4 + 3) * XS + lane];
            acc0 = fmaf(v0.x, xa, acc0); acc1 = fmaf(v1.x, xa, acc1);
            acc0 = fmaf(v0.y, xb, acc0); acc1 = fmaf(v1.y, xb, acc1);
            acc0 = fmaf(v0.z, xc, acc0); acc1 = fmaf(v1.z, xc, acc1);
            acc0 = fmaf(v0.w, xd, acc0); acc1 = fmaf(v1.w, xd, acc1);
        }
        #pragma unroll
        for (int j = 48; j < 51; j++) {
            float xv = Xin[j * XS + lane];
            acc0 = fmaf(a0[j], xv, acc0);
            acc1 = fmaf(a1[j], xv, acc1);
        }
        Hout[i0 * XS + lane] = acc0;
        if (has1) Hout[i1 * XS + lane] = acc1;
    }
    __syncthreads();
}

__global__ void __launch_bounds__(NT, 3) value_net_kernel(
    const float* __restrict__ state,
    const float* __restrict__ wr_w0, const float* __restrict__ wr_b0,
    const float* __restrict__ wr_w1, const float* __restrict__ wr_b1,
    const float* __restrict__ wh_w0, const float* __restrict__ wh_b0,
    const float* __restrict__ wh_w1, const float* __restrict__ wh_b1,
    const float* __restrict__ g0_w0, const float* __restrict__ g0_b0,
    const float* __restrict__ g0_w1, const float* __restrict__ g0_b1,
    const float* __restrict__ g1_w0, const float* __restrict__ g1_b0,
    const float* __restrict__ g1_w1, const float* __restrict__ g1_b1,
    const float* __restrict__ v_w0, const float* __restrict__ v_b0,
    const float* __restrict__ v_w1, const float* __restrict__ v_b1,
    const float* __restrict__ v_w2, const float* __restrict__ v_b2,
    float* __restrict__ out)
{
    extern __shared__ float sm[];
    float* sX  = sm + OFF_X;
    float* sH  = sm + OFF_H;
    float* sPi = sm + OFF_PI;   // emb hidden / Pi / final MLP scratch
    float* sW  = sm + OFF_W;
    float* sSt = sm + OFF_ST;
    float* sO  = sm + OFF_O;

    const int tid = threadIdx.x;
    const int wid = tid >> 5;
    const int lane = tid & 31;
    const int b = blockIdx.x;

    // ---- stage state row (50x15) and embedding MLP1 weights
    const float* stb = state + b * 750;
    for (int i = tid; i < 750; i += NT) sSt[i] = stb[i];
    for (int i = tid; i < 384; i += NT) sW[i] = wh_w0[i];          // (6,64)
    for (int i = tid; i < 576; i += NT) sW[448 + i] = wr_w0[i];    // (9,64)
    if (tid < 64)       sW[384 + tid]          = wh_b0[tid];
    else if (tid < 128) sW[1024 + (tid - 64)]  = wr_b0[tid - 64];
    __syncthreads();

    // ---- embedding MLP layer 1: hidden (stride HIDS) in sPi
    for (int idx = tid; idx < 3200; idx += NT) {
        int n = idx >> 6, c = idx & 63;
        const float* hr = sSt + n * 15 + 9;
        float acc = sW[384 + c];
        #pragma unroll
        for (int f = 0; f < 6; f++) acc = fmaf(hr[f], sW[f * 64 + c], acc);
        sPi[n * HIDS + c] = fmaxf(acc, 0.f);
    }
    if (tid < 64) {   // robot hidden
        float acc = sW[1024 + tid];
        #pragma unroll
        for (int f = 0; f < 9; f++) acc = fmaf(sSt[f], sW[448 + f * 64 + tid], acc);
        sPi[ROBOT_HID + tid] = fmaxf(acc, 0.f);
    }
    __syncthreads();

    // ---- stage embedding MLP2 weights
    for (int i = tid; i < 2048; i += NT) sW[i] = wh_w1[i];           // (64,32)
    for (int i = tid; i < 2048; i += NT) sW[2080 + i] = wr_w1[i];    // (64,32)
    if (tid < 32)      sW[2048 + tid]         = wh_b1[tid];
    else if (tid < 64) sW[4128 + (tid - 32)]  = wr_b1[tid - 32];
    __syncthreads();

    // ---- embedding MLP layer 2 -> X (51 x 32): 4 rows x 4 cols tiles
    {
        int tq = tid & 7;
        for (int nq = tid >> 3; nq < 13; nq += NT / 8) {
            int n0 = nq * 4;
            const float4* h0 = (const float4*)(sPi + (n0 + 0) * HIDS);
            const float4* h1 = (const float4*)(sPi + (n0 + 1) * HIDS);
            const float4* h2 = (const float4*)(sPi + (n0 + 2) * HIDS);
            const float4* h3 = (const float4*)(sPi + (n0 + 3) * HIDS);
            float4 bv = ((const float4*)(sW + 2048))[tq];
            float4 a0 = bv, a1 = bv, a2 = bv, a3 = bv;
            #pragma unroll 4
            for (int c4 = 0; c4 < 16; c4++) {
                float4 v0 = h0[c4], v1 = h1[c4], v2 = h2[c4], v3 = h3[c4];
                #pragma unroll
                for (int s = 0; s < 4; s++) {
                    float4 wv = ((const float4*)(sW + (c4 * 4 + s) * 32))[tq];
                    fma4(a0, comp(v0, s), wv);
                    fma4(a1, comp(v1, s), wv);
                    fma4(a2, comp(v2, s), wv);
                    fma4(a3, comp(v3, s), wv);
                }
            }
            relu4(a0); relu4(a1); relu4(a2); relu4(a3);
            ((float4*)(sX + (n0 + 1) * XS))[tq] = a0;
            if (n0 + 1 < 50) ((float4*)(sX + (n0 + 2) * XS))[tq] = a1;
            if (n0 + 2 < 50) ((float4*)(sX + (n0 + 3) * XS))[tq] = a2;
            if (n0 + 3 < 50) ((float4*)(sX + (n0 + 4) * XS))[tq] = a3;
        }
    }
    if (tid < 8) {   // robot embedding -> X[0]
        int q = tid;
        const float4* hid4 = (const float4*)(sPi + ROBOT_HID);
        float4 acc = ((const float4*)(sW + 4128))[q];
        #pragma unroll 4
        for (int c4 = 0; c4 < 16; c4++) {
            float4 h = hid4[c4];
            #pragma unroll
            for (int s = 0; s < 4; s++)
                fma4(acc, comp(h, s), ((const float4*)(sW + 2080 + (c4 * 4 + s) * 32))[q]);
        }
        relu4(acc);
        ((float4*)sX)[q] = acc;
    }
    __syncthreads();

    // ---- GAT layer 1 (full), GAT layer 2 (row 0 only — output uses node 0 only)
    gat_layer<true >(sm, sX, sH, g0_w0, g0_b0, g0_w1, g0_b1, tid, wid, lane);
    gat_layer<false>(sm, sH, sO, g1_w0, g1_b0, g1_w1, g1_b1, tid, wid, lane);

    // ---- combine: out0 = H1[0] + H2[0] + X[0]
    if (tid < 32) sO[tid] = sO[tid] + sH[tid] + sX[tid];
    __syncthreads();

    // ---- value MLP: 32 -> 150 -> 100 -> 1, relu each (weights via L2/__ldg)
    float* h1 = sPi;         // 150
    float* h2 = sPi + 256;   // 100
    for (int c = tid; c < 150; c += NT) {
        float acc = __ldg(v_b0 + c);
        #pragma unroll 8
        for (int f = 0; f < 32; f++) acc = fmaf(sO[f], __ldg(v_w0 + f * 150 + c), acc);
        h1[c] = fmaxf(acc, 0.f);
    }
    __syncthreads();
    for (int c = tid; c < 100; c += NT) {
        float acc = __ldg(v_b1 + c);
        #pragma unroll 10
        for (int f = 0; f < 150; f++) acc = fmaf(h1[f], __ldg(v_w1 + f * 100 + c), acc);
        h2[c] = fmaxf(acc, 0.f);
    }
    __syncthreads();
    if (tid < 32) {
        float acc = 0.f;
        #pragma unroll
        for (int f = lane; f < 100; f += 32) acc = fmaf(h2[f], __ldg(v_w2 + f), acc);
        #pragma unroll
        for (int off = 16; off > 0; off >>= 1)
            acc += __shfl_xor_sync(0xffffffffu, acc, off);
        if (lane == 0) out[b] = fmaxf(acc + __ldg(v_b2), 0.f);
    }
}

extern "C" void kernel_launch(void* const* d_in, const int* in_sizes, int n_in,
                              void* d_out, int out_size)
{
    const float* state = (const float*)d_in[0];
    // d_in[1] = dropout (unused)
    const float* wr_w0 = (const float*)d_in[2];
    const float* wr_b0 = (const float*)d_in[3];
    const float* wr_w1 = (const float*)d_in[4];
    const float* wr_b1 = (const float*)d_in[5];
    const float* wh_w0 = (const float*)d_in[6];
    const float* wh_b0 = (const float*)d_in[7];
    const float* wh_w1 = (const float*)d_in[8];
    const float* wh_b1 = (const float*)d_in[9];
    const float* g0_w0 = (const float*)d_in[10];
    const float* g0_b0 = (const float*)d_in[11];
    const float* g0_w1 = (const float*)d_in[12];
    const float* g0_b1 = (const float*)d_in[13];
    const float* g1_w0 = (const float*)d_in[14];
    const float* g1_b0 = (const float*)d_in[15];
    const float* g1_w1 = (const float*)d_in[16];
    const float* g1_b1 = (const float*)d_in[17];
    const float* v_w0  = (const float*)d_in[18];
    const float* v_b0  = (const float*)d_in[19];
    const float* v_w1  = (const float*)d_in[20];
    const float* v_b1  = (const float*)d_in[21];
    const float* v_w2  = (const float*)d_in[22];
    const float* v_b2  = (const float*)d_in[23];
    float* out = (float*)d_out;

    int B = in_sizes[0] / 750;
    size_t smem = SMEM_FLOATS * sizeof(float);
    cudaFuncSetAttribute(value_net_kernel,
                         cudaFuncAttributeMaxDynamicSharedMemorySize, (int)smem);
    value_net_kernel<<<B, NT, smem>>>(
        state,
        wr_w0, wr_b0, wr_w1, wr_b1,
        wh_w0, wh_b0, wh_w1, wh_b1,
        g0_w0, g0_b0, g0_w1, g0_b1,
        g1_w0, g1_b0, g1_w1, g1_b1,
        v_w0, v_b0, v_w1, v_b1, v_w2, v_b2,
        out);
}

// round 7
// speedup vs baseline: 1.3226x; 1.3226x over previous
#include <cuda_runtime.h>

#define NT 256
#define XS   36    // X/H row stride (floats) — 144B rotates banks
#define PJS  68    // Pj row stride
#define HIDS 68    // emb hidden row stride
#define ATTS 52

// shared layout (float offsets)
#define OFF_X    0        // 51*36 = 1836
#define OFF_H    1840     // 51*36 = 1836
#define OFF_PI   3680     // emb hidden 50*68+64=3464 / Pi 51*64=3264 / mlp scratch
#define OFF_PJ   7216     // 51*68 = 3468
#define OFF_ATT  10688    // 51*52 = 2652
#define OFF_W    13344    // weights: emb 5248 | G1 4232 | G2 4232
#define OFF_WE   OFF_W               // emb1 (1088) + emb2 (4160)
#define OFF_WG1  (OFF_W + 5248)
#define OFF_WG2  (OFF_W + 5248 + 4232)
#define OFF_ST   (OFF_W + 5248 + 4232 + 4232)   // 27056, state 750
#define OFF_O    27808    // 64
#define SMEM_FLOATS 27872
#define ROBOT_HID 3468    // robot hidden inside PI region

__device__ __forceinline__ void fma4(float4& acc, float s, const float4 w) {
    acc.x = fmaf(s, w.x, acc.x);
    acc.y = fmaf(s, w.y, acc.y);
    acc.z = fmaf(s, w.z, acc.z);
    acc.w = fmaf(s, w.w, acc.w);
}
__device__ __forceinline__ float comp(const float4 v, int s) {
    return s == 0 ? v.x : s == 1 ? v.y : s == 2 ? v.z : v.w;
}
__device__ __forceinline__ void relu4(float4& a) {
    a.x = fmaxf(a.x, 0.f); a.y = fmaxf(a.y, 0.f);
    a.z = fmaxf(a.z, 0.f); a.w = fmaxf(a.w, 0.f);
}

// softmax without max-subtract (shift-invariant; logits are tiny here)
__device__ __forceinline__ void softmax_row(
    float accA, float accB, float b1v, int i, int lane, int jb, bool vb,
    float* __restrict__ sAtt)
{
    float Aa = accA + b1v;
    float Ab = accB + b1v;
    float ea = Aa > 0.f ? Aa : 0.04f * Aa;   // leaky relu
    float eb = Ab > 0.f ? Ab : 0.04f * Ab;
    bool va = (i == 0) || (lane != 0);       // adj: rows >=1 exclude j==0
    float pa = va ? __expf(ea) : 0.f;
    float pb = vb ? __expf(eb) : 0.f;
    float s = pa + pb;
    #pragma unroll
    for (int off = 16; off > 0; off >>= 1)
        s += __shfl_xor_sync(0xffffffffu, s, off);
    float inv = 1.0f / s;
    sAtt[i * ATTS + lane] = pa * inv;
    if (vb) sAtt[i * ATTS + jb] = pb * inv;
}

// GAT layer 1: full 51-row layer. Weights pre-staged in sWg.
__device__ __forceinline__ void gat_full(
    float* sm, const float* __restrict__ sWg,
    const float* __restrict__ Xin, float* __restrict__ Hout,
    int tid, int wid, int lane)
{
    float* sPi  = sm + OFF_PI;
    float* sPj  = sm + OFF_PJ;
    float* sAtt = sm + OFF_ATT;

    // ---- P phase: 4 nodes x 4 cols outer-product tile per 16-thread group
    {
        int tq = tid & 15, nq = tid >> 4;
        if (nq < 13) {
            int n0 = nq * 4;
            const float4* x0 = (const float4*)(Xin + (n0 + 0) * XS);
            const float4* x1 = (const float4*)(Xin + (n0 + 1) * XS);
            const float4* x2 = (const float4*)(Xin + (n0 + 2) * XS);
            const float4* x3 = (const float4*)(Xin + (n0 + 3) * XS);
            float4 z = make_float4(0.f, 0.f, 0.f, 0.f);
            float4 aJ0 = z, aJ1 = z, aJ2 = z, aJ3 = z;
            float4 bI = ((const float4*)(sWg + 4096))[tq];
            float4 aI0 = bI, aI1 = bI, aI2 = bI, aI3 = bI;
            #pragma unroll 4
            for (int f4 = 0; f4 < 8; f4++) {
                float4 xv0 = x0[f4], xv1 = x1[f4], xv2 = x2[f4], xv3 = x3[f4];
                #pragma unroll
                for (int s = 0; s < 4; s++) {
                    int f = f4 * 4 + s;
                    float4 wI = ((const float4*)(sWg + f * 64))[tq];
                    float4 wJ = ((const float4*)(sWg + (f + 32) * 64))[tq];
                    float e0 = comp(xv0, s), e1 = comp(xv1, s);
                    float e2 = comp(xv2, s), e3 = comp(xv3, s);
                    fma4(aI0, e0, wI); fma4(aI1, e1, wI);
                    fma4(aI2, e2, wI); fma4(aI3, e3, wI);
                    fma4(aJ0, e0, wJ); fma4(aJ1, e1, wJ);
                    fma4(aJ2, e2, wJ); fma4(aJ3, e3, wJ);
                }
            }
            ((float4*)(sPi + (n0 + 0) * 64))[tq] = aI0;
            ((float4*)(sPi + (n0 + 1) * 64))[tq] = aI1;
            ((float4*)(sPi + (n0 + 2) * 64))[tq] = aI2;
            if (n0 + 3 < 51) ((float4*)(sPi + (n0 + 3) * 64))[tq] = aI3;
            ((float4*)(sPj + (n0 + 0) * PJS))[tq] = aJ0;
            ((float4*)(sPj + (n0 + 1) * PJS))[tq] = aJ1;
            ((float4*)(sPj + (n0 + 2) * PJS))[tq] = aJ2;
            if (n0 + 3 < 51) ((float4*)(sPj + (n0 + 3) * PJS))[tq] = aJ3;
        }
    }
    __syncthreads();

    // ---- pair phase, 2 rows per iteration (pa/pb/w1 reused across both rows)
    for (int i0 = wid; i0 < 51; i0 += 16) {
        int i1 = i0 + 8;
        bool has1 = i1 < 51;
        int i1c = has1 ? i1 : i0;
        int jb  = lane + 32;
        int jbc = jb < 51 ? jb : 50;       // clamp keeps LDS conflict-free
        const float4* p0v = (const float4*)(sPi + i0 * 64);
        const float4* p1v = (const float4*)(sPi + i1c * 64);
        const float4* w1v = (const float4*)(sWg + 4160);
        const float4* pav = (const float4*)(sPj + lane * PJS);
        const float4* pbv = (const float4*)(sPj + jbc * PJS);
        float aA0 = 0.f, aB0 = 0.f, aA1 = 0.f, aB1 = 0.f;
        #pragma unroll 8
        for (int c4 = 0; c4 < 16; c4++) {
            float4 pa = pav[c4];
            float4 pb = pbv[c4];
            float4 w1 = w1v[c4];
            float4 p0 = p0v[c4];
            float4 p1 = p1v[c4];
            aA0 = fmaf(fmaxf(p0.x + pa.x, 0.f), w1.x, aA0);
            aA0 = fmaf(fmaxf(p0.y + pa.y, 0.f), w1.y, aA0);
            aA0 = fmaf(fmaxf(p0.z + pa.z, 0.f), w1.z, aA0);
            aA0 = fmaf(fmaxf(p0.w + pa.w, 0.f), w1.w, aA0);
            aB0 = fmaf(fmaxf(p0.x + pb.x, 0.f), w1.x, aB0);
            aB0 = fmaf(fmaxf(p0.y + pb.y, 0.f), w1.y, aB0);
            aB0 = fmaf(fmaxf(p0.z + pb.z, 0.f), w1.z, aB0);
            aB0 = fmaf(fmaxf(p0.w + pb.w, 0.f), w1.w, aB0);
            aA1 = fmaf(fmaxf(p1.x + pa.x, 0.f), w1.x, aA1);
            aA1 = fmaf(fmaxf(p1.y + pa.y, 0.f), w1.y, aA1);
            aA1 = fmaf(fmaxf(p1.z + pa.z, 0.f), w1.z, aA1);
            aA1 = fmaf(fmaxf(p1.w + pa.w, 0.f), w1.w, aA1);
            aB1 = fmaf(fmaxf(p1.x + pb.x, 0.f), w1.x, aB1);
            aB1 = fmaf(fmaxf(p1.y + pb.y, 0.f), w1.y, aB1);
            aB1 = fmaf(fmaxf(p1.z + pb.z, 0.f), w1.z, aB1);
            aB1 = fmaf(fmaxf(p1.w + pb.w, 0.f), w1.w, aB1);
        }
        float b1v = sWg[4224];
        bool vb = jb < 51;
        softmax_row(aA0, aB0, b1v, i0, lane, jb, vb, sAtt);
        if (has1) softmax_row(aA1, aB1, b1v, i1, lane, jb, vb, sAtt);
    }
    __syncthreads();

    // ---- H = att @ Xin, 2 rows per iteration (X loads shared)
    for (int i0 = wid; i0 < 51; i0 += 16) {
        int i1 = i0 + 8;
        bool has1 = i1 < 51;
        int i1c = has1 ? i1 : i0;
        const float* a0 = sAtt + i0 * ATTS;
        const float* a1 = sAtt + i1c * ATTS;
        const float4* a04 = (const float4*)a0;
        const float4* a14 = (const float4*)a1;
        float acc0 = 0.f, acc1 = 0.f;
        #pragma unroll
        for (int j4 = 0; j4 < 12; j4++) {
            float4 v0 = a04[j4];
            float4 v1 = a14[j4];
            float xa = Xin[(j4 * 4 + 0) * XS + lane];
            float xb = Xin[(j4 * 4 + 1) * XS + lane];
            float xc = Xin[(j4 * 4 + 2) * XS + lane];
            float xd = Xin[(j4 * 4 + 3) * XS + lane];
            acc0 = fmaf(v0.x, xa, acc0); acc1 = fmaf(v1.x, xa, acc1);
            acc0 = fmaf(v0.y, xb, acc0); acc1 = fmaf(v1.y, xb, acc1);
            acc0 = fmaf(v0.z, xc, acc0); acc1 = fmaf(v1.z, xc, acc1);
            acc0 = fmaf(v0.w, xd, acc0); acc1 = fmaf(v1.w, xd, acc1);
        }
        #pragma unroll
        for (int j = 48; j < 51; j++) {
            float xv = Xin[j * XS + lane];
            acc0 = fmaf(a0[j], xv, acc0);
            acc1 = fmaf(a1[j], xv, acc1);
        }
        Hout[i0 * XS + lane] = acc0;
        if (has1) Hout[i1 * XS + lane] = acc1;
    }
    __syncthreads();
}

__global__ void __launch_bounds__(NT, 2) value_net_kernel(
    const float* __restrict__ state,
    const float* __restrict__ wr_w0, const float* __restrict__ wr_b0,
    const float* __restrict__ wr_w1, const float* __restrict__ wr_b1,
    const float* __restrict__ wh_w0, const float* __restrict__ wh_b0,
    const float* __restrict__ wh_w1, const float* __restrict__ wh_b1,
    const float* __restrict__ g0_w0, const float* __restrict__ g0_b0,
    const float* __restrict__ g0_w1, const float* __restrict__ g0_b1,
    const float* __restrict__ g1_w0, const float* __restrict__ g1_b0,
    const float* __restrict__ g1_w1, const float* __restrict__ g1_b1,
    const float* __restrict__ v_w0, const float* __restrict__ v_b0,
    const float* __restrict__ v_w1, const float* __restrict__ v_b1,
    const float* __restrict__ v_w2, const float* __restrict__ v_b2,
    float* __restrict__ out)
{
    extern __shared__ float sm[];
    float* sX   = sm + OFF_X;
    float* sH   = sm + OFF_H;
    float* sPi  = sm + OFF_PI;   // emb hidden / Pi / final MLP scratch
    float* sPj  = sm + OFF_PJ;
    float* sAtt = sm + OFF_ATT;
    float* sWE  = sm + OFF_WE;
    float* sW2  = sm + OFF_WE + 1088;   // emb2 weights
    float* sWG1 = sm + OFF_WG1;
    float* sWG2 = sm + OFF_WG2;
    float* sSt  = sm + OFF_ST;
    float* sO   = sm + OFF_O;

    const int tid = threadIdx.x;
    const int wid = tid >> 5;
    const int lane = tid & 31;
    const int b = blockIdx.x;

    // ---- stage EVERYTHING once: state + all weights (high MLP up front)
    {
        const float* stb = state + b * 750;
        for (int i = tid; i < 750; i += NT) sSt[i] = stb[i];
        for (int i = tid; i < 384; i += NT) sWE[i] = wh_w0[i];
        for (int i = tid; i < 576; i += NT) sWE[448 + i] = wr_w0[i];
        if (tid < 64)       sWE[384 + tid]  = wh_b0[tid];
        else if (tid < 128) sWE[1024 + (tid - 64)] = wr_b0[tid - 64];
        // emb2: wh_w1 @0, wh_b1 @2048, wr_w1 @2080, wr_b1 @4128 (within sW2)
        for (int i = tid; i < 512; i += NT) ((float4*)sW2)[i] = ((const float4*)wh_w1)[i];
        for (int i = tid; i < 512; i += NT)
            ((float4*)(sW2 + 2080))[i] = ((const float4*)wr_w1)[i];
        if (tid < 32)      sW2[2048 + tid] = wh_b1[tid];
        else if (tid < 64) sW2[4128 + (tid - 32)] = wr_b1[tid - 32];
        // GAT1 weights
        for (int i = tid; i < 1024; i += NT) ((float4*)sWG1)[i] = ((const float4*)g0_w0)[i];
        if (tid < 64)       sWG1[4096 + tid] = g0_b0[tid];
        else if (tid < 128) sWG1[4160 + (tid - 64)] = g0_w1[tid - 64];
        else if (tid == 128) sWG1[4224] = g0_b1[0];
        // GAT2 weights
        for (int i = tid; i < 1024; i += NT) ((float4*)sWG2)[i] = ((const float4*)g1_w0)[i];
        if (tid < 64)       sWG2[4096 + tid] = g1_b0[tid];
        else if (tid < 128) sWG2[4160 + (tid - 64)] = g1_w1[tid - 64];
        else if (tid == 128) sWG2[4224] = g1_b1[0];
    }
    __syncthreads();

    // ---- embedding MLP layer 1: hidden (stride HIDS) in sPi
    for (int idx = tid; idx < 3200; idx += NT) {
        int n = idx >> 6, c = idx & 63;
        const float* hr = sSt + n * 15 + 9;
        float acc = sWE[384 + c];
        #pragma unroll
        for (int f = 0; f < 6; f++) acc = fmaf(hr[f], sWE[f * 64 + c], acc);
        sPi[n * HIDS + c] = fmaxf(acc, 0.f);
    }
    if (tid < 64) {   // robot hidden
        float acc = sWE[1024 + tid];
        #pragma unroll
        for (int f = 0; f < 9; f++) acc = fmaf(sSt[f], sWE[448 + f * 64 + tid], acc);
        sPi[ROBOT_HID + tid] = fmaxf(acc, 0.f);
    }
    __syncthreads();

    // ---- embedding MLP layer 2 -> X (51 x 32): 4 rows x 4 cols tiles
    {
        int tq = tid & 7, nq = tid >> 3;
        if (nq < 13) {
            int n0 = nq * 4;
            const float4* h0 = (const float4*)(sPi + (n0 + 0) * HIDS);
            const float4* h1 = (const float4*)(sPi + (n0 + 1) * HIDS);
            const float4* h2 = (const float4*)(sPi + (n0 + 2) * HIDS);
            const float4* h3 = (const float4*)(sPi + (n0 + 3) * HIDS);
            float4 bv = ((const float4*)(sW2 + 2048))[tq];
            float4 a0 = bv, a1 = bv, a2 = bv, a3 = bv;
            #pragma unroll 4
            for (int c4 = 0; c4 < 16; c4++) {
                float4 v0 = h0[c4], v1 = h1[c4], v2 = h2[c4], v3 = h3[c4];
                #pragma unroll
                for (int s = 0; s < 4; s++) {
                    float4 wv = ((const float4*)(sW2 + (c4 * 4 + s) * 32))[tq];
                    fma4(a0, comp(v0, s), wv);
                    fma4(a1, comp(v1, s), wv);
                    fma4(a2, comp(v2, s), wv);
                    fma4(a3, comp(v3, s), wv);
                }
            }
            relu4(a0); relu4(a1); relu4(a2); relu4(a3);
            ((float4*)(sX + (n0 + 1) * XS))[tq] = a0;
            if (n0 + 1 < 50) ((float4*)(sX + (n0 + 2) * XS))[tq] = a1;
            if (n0 + 2 < 50) ((float4*)(sX + (n0 + 3) * XS))[tq] = a2;
            if (n0 + 3 < 50) ((float4*)(sX + (n0 + 4) * XS))[tq] = a3;
        }
    }
    if (tid < 8) {   // robot embedding -> X[0]
        int q = tid;
        const float4* hid4 = (const float4*)(sPi + ROBOT_HID);
        float4 acc = ((const float4*)(sW2 + 4128))[q];
        #pragma unroll 4
        for (int c4 = 0; c4 < 16; c4++) {
            float4 h = hid4[c4];
            #pragma unroll
            for (int s = 0; s < 4; s++)
                fma4(acc, comp(h, s), ((const float4*)(sW2 + 2080 + (c4 * 4 + s) * 32))[q]);
        }
        relu4(acc);
        ((float4*)sX)[q] = acc;
    }
    __syncthreads();

    // ---- GAT layer 1 (full)
    gat_full(sm, sWG1, sX, sH, tid, wid, lane);

    // ---- GAT layer 2, row 0 only. P phase: Pj for all j (from sH), Pi row 0.
    {
        int tq = tid & 15, nq = tid >> 4;
        if (nq < 13) {
            int n0 = nq * 4;
            const float4* x0 = (const float4*)(sH + (n0 + 0) * XS);
            const float4* x1 = (const float4*)(sH + (n0 + 1) * XS);
            const float4* x2 = (const float4*)(sH + (n0 + 2) * XS);
            const float4* x3 = (const float4*)(sH + (n0 + 3) * XS);
            float4 z = make_float4(0.f, 0.f, 0.f, 0.f);
            float4 aJ0 = z, aJ1 = z, aJ2 = z, aJ3 = z;
            #pragma unroll 4
            for (int f4 = 0; f4 < 8; f4++) {
                float4 xv0 = x0[f4], xv1 = x1[f4], xv2 = x2[f4], xv3 = x3[f4];
                #pragma unroll
                for (int s = 0; s < 4; s++) {
                    float4 wJ = ((const float4*)(sWG2 + (f4 * 4 + s + 32) * 64))[tq];
                    fma4(aJ0, comp(xv0, s), wJ);
                    fma4(aJ1, comp(xv1, s), wJ);
                    fma4(aJ2, comp(xv2, s), wJ);
                    fma4(aJ3, comp(xv3, s), wJ);
                }
            }
            ((float4*)(sPj + (n0 + 0) * PJS))[tq] = aJ0;
            ((float4*)(sPj + (n0 + 1) * PJS))[tq] = aJ1;
            ((float4*)(sPj + (n0 + 2) * PJS))[tq] = aJ2;
            if (n0 + 3 < 51) ((float4*)(sPj + (n0 + 3) * PJS))[tq] = aJ3;
        }
        if (tid >= 208 && tid < 224) {    // Pi row 0 (idle 16-group)
            int q = tid - 208;
            const float4* x4p = (const float4*)sH;
            float4 aI = ((const float4*)(sWG2 + 4096))[q];
            #pragma unroll
            for (int f4 = 0; f4 < 8; f4++) {
                float4 xv = x4p[f4];
                #pragma unroll
                for (int s = 0; s < 4; s++)
                    fma4(aI, comp(xv, s), ((const float4*)(sWG2 + (f4 * 4 + s) * 64))[q]);
            }
            ((float4*)sPi)[q] = aI;
        }
    }
    __syncthreads();

    // ---- GAT2 tail: warp 0 does pair+softmax+H+combine (no block barriers inside)
    if (wid == 0) {
        int jb  = lane + 32;
        int jbc = jb < 51 ? jb : 50;
        bool vb = jb < 51;
        const float4* p0v = (const float4*)sPi;
        const float4* w1v = (const float4*)(sWG2 + 4160);
        const float4* pav = (const float4*)(sPj + lane * PJS);
        const float4* pbv = (const float4*)(sPj + jbc * PJS);
        float aA = 0.f, aB = 0.f;
        #pragma unroll 8
        for (int c4 = 0; c4 < 16; c4++) {
            float4 pa = pav[c4];
            float4 pb = pbv[c4];
            float4 w1 = w1v[c4];
            float4 p0 = p0v[c4];
            aA = fmaf(fmaxf(p0.x + pa.x, 0.f), w1.x, aA);
            aA = fmaf(fmaxf(p0.y + pa.y, 0.f), w1.y, aA);
            aA = fmaf(fmaxf(p0.z + pa.z, 0.f), w1.z, aA);
            aA = fmaf(fmaxf(p0.w + pa.w, 0.f), w1.w, aA);
            aB = fmaf(fmaxf(p0.x + pb.x, 0.f), w1.x, aB);
            aB = fmaf(fmaxf(p0.y + pb.y, 0.f), w1.y, aB);
            aB = fmaf(fmaxf(p0.z + pb.z, 0.f), w1.z, aB);
            aB = fmaf(fmaxf(p0.w + pb.w, 0.f), w1.w, aB);
        }
        softmax_row(aA, aB, sWG2[4224], 0, lane, jb, vb, sAtt);
        __syncwarp();
        // H2 row 0 + combine (Xin = sH)
        const float* a0 = sAtt;
        const float4* a04 = (const float4*)a0;
        float acc = 0.f;
        #pragma unroll
        for (int j4 = 0; j4 < 12; j4++) {
            float4 v0 = a04[j4];
            acc = fmaf(v0.x, sH[(j4 * 4 + 0) * XS + lane], acc);
            acc = fmaf(v0.y, sH[(j4 * 4 + 1) * XS + lane], acc);
            acc = fmaf(v0.z, sH[(j4 * 4 + 2) * XS + lane], acc);
            acc = fmaf(v0.w, sH[(j4 * 4 + 3) * XS + lane], acc);
        }
        #pragma unroll
        for (int j = 48; j < 51; j++)
            acc = fmaf(a0[j], sH[j * XS + lane], acc);
        // combine: out0 = H1[0] + H2[0] + X[0]
        sO[lane] = acc + sH[lane] + sX[lane];
    }
    __syncthreads();

    // ---- value MLP: 32 -> 150 -> 100 -> 1, relu each (weights via L2/__ldg)
    float* h1 = sPi;         // 150
    float* h2 = sPi + 256;   // 100
    for (int c = tid; c < 150; c += NT) {
        float acc = __ldg(v_b0 + c);
        #pragma unroll 8
        for (int f = 0; f < 32; f++) acc = fmaf(sO[f], __ldg(v_w0 + f * 150 + c), acc);
        h1[c] = fmaxf(acc, 0.f);
    }
    __syncthreads();
    for (int c = tid; c < 100; c += NT) {
        float acc0 = __ldg(v_b1 + c);
        float acc1 = 0.f;
        #pragma unroll 10
        for (int f = 0; f < 150; f += 2) {
            acc0 = fmaf(h1[f],     __ldg(v_w1 + f * 100 + c),       acc0);
            acc1 = fmaf(h1[f + 1], __ldg(v_w1 + (f + 1) * 100 + c), acc1);
        }
        h2[c] = fmaxf(acc0 + acc1, 0.f);
    }
    __syncthreads();
    if (tid < 32) {
        float acc = 0.f;
        #pragma unroll
        for (int f = lane; f < 100; f += 32) acc = fmaf(h2[f], __ldg(v_w2 + f), acc);
        #pragma unroll
        for (int off = 16; off > 0; off >>= 1)
            acc += __shfl_xor_sync(0xffffffffu, acc, off);
        if (lane == 0) out[b] = fmaxf(acc + __ldg(v_b2), 0.f);
    }
}

extern "C" void kernel_launch(void* const* d_in, const int* in_sizes, int n_in,
                              void* d_out, int out_size)
{
    const float* state = (const float*)d_in[0];
    // d_in[1] = dropout (unused)
    const float* wr_w0 = (const float*)d_in[2];
    const float* wr_b0 = (const float*)d_in[3];
    const float* wr_w1 = (const float*)d_in[4];
    const float* wr_b1 = (const float*)d_in[5];
    const float* wh_w0 = (const float*)d_in[6];
    const float* wh_b0 = (const float*)d_in[7];
    const float* wh_w1 = (const float*)d_in[8];
    const float* wh_b1 = (const float*)d_in[9];
    const float* g0_w0 = (const float*)d_in[10];
    const float* g0_b0 = (const float*)d_in[11];
    const float* g0_w1 = (const float*)d_in[12];
    const float* g0_b1 = (const float*)d_in[13];
    const float* g1_w0 = (const float*)d_in[14];
    const float* g1_b0 = (const float*)d_in[15];
    const float* g1_w1 = (const float*)d_in[16];
    const float* g1_b1 = (const float*)d_in[17];
    const float* v_w0  = (const float*)d_in[18];
    const float* v_b0  = (const float*)d_in[19];
    const float* v_w1  = (const float*)d_in[20];
    const float* v_b1  = (const float*)d_in[21];
    const float* v_w2  = (const float*)d_in[22];
    const float* v_b2  = (const float*)d_in[23];
    float* out = (float*)d_out;

    int B = in_sizes[0] / 750;
    size_t smem = SMEM_FLOATS * sizeof(float);
    cudaFuncSetAttribute(value_net_kernel,
                         cudaFuncAttributeMaxDynamicSharedMemorySize, (int)smem);
    value_net_kernel<<<B, NT, smem>>>(
        state,
        wr_w0, wr_b0, wr_w1, wr_b1,
        wh_w0, wh_b0, wh_w1, wh_b1,
        g0_w0, g0_b0, g0_w1, g0_b1,
        g1_w0, g1_b0, g1_w1, g1_b1,
        v_w0, v_b0, v_w1, v_b1, v_w2, v_b2,
        out);
}